// round 10
// baseline (speedup 1.0000x reference)
#include <cuda_runtime.h>
#include <cstdint>

#define GS 7
#define CCH 30
#define CPT 128                        // cells per tile
#define TPB 128                        // threads per block
#define NST 3                          // pipeline stages
#define TENSOR_F4 960                  // float4 per tensor per tile (128*30/4)
#define STAGE_F4 (2 * TENSOR_F4)       // 1920 (in + tg)
#define STAGE_BYTES (STAGE_F4 * 16)    // 30720
#define DYN_SMEM (NST * STAGE_BYTES)   // 92160

// Zero-initialized at module load; last-block finalize resets via atomicExch.
__device__ float g_acc[3];
__device__ unsigned int g_count;

__device__ __forceinline__ uint32_t smem_u32(const void* p) {
    return (uint32_t)__cvta_generic_to_shared(p);
}

// Issue one stage's coalesced loads (all 128 threads participate), then commit
// a group. ALWAYS commits (possibly empty) so group counting stays uniform.
__device__ __forceinline__ void issue_stage(
    char* sbase, const float4* __restrict__ in4, const float4* __restrict__ tg4,
    long long tile, int ntiles, long long n4, int tid)
{
    if (tile < (long long)ntiles) {
        uint32_t dst = smem_u32(sbase);
        long long base4 = tile * TENSOR_F4;
        #pragma unroll
        for (int i = 0; i < 15; i++) {
            int g = i * TPB + tid;              // 0..1919 within stage
            const float4* src;
            long long s4;
            if (g < TENSOR_F4) { s4 = base4 + g;              src = in4 + s4; }
            else               { s4 = base4 + (g - TENSOR_F4); src = tg4 + s4; }
            if (s4 < n4) {
                asm volatile("cp.async.cg.shared.global [%0], [%1], 16;"
                             :: "r"(dst + (uint32_t)g * 16), "l"(src) : "memory");
            }
        }
    }
    asm volatile("cp.async.commit_group;" ::: "memory");
}

__global__ __launch_bounds__(TPB) void yolo_loss_kernel(
    const float* __restrict__ in_, const float* __restrict__ tg_,
    float* __restrict__ out, int ncells, int ntiles, float inv_bs)
{
    extern __shared__ __align__(16) char dynbuf[];
    __shared__ float sb[3][4];

    int tid = threadIdx.x;
    int bid = blockIdx.x;
    int grid = gridDim.x;
    const float4* in4 = reinterpret_cast<const float4*>(in_);
    const float4* tg4 = reinterpret_cast<const float4*>(tg_);
    long long n4 = ((long long)ncells * CCH) / 4;

    int nt = (bid < ntiles) ? (ntiles - bid + grid - 1) / grid : 0;

    // Prologue: fill first two stages (empty commits beyond range keep counts uniform)
    issue_stage(dynbuf + 0 * STAGE_BYTES, in4, tg4, (long long)bid,        ntiles, n4, tid);
    issue_stage(dynbuf + 1 * STAGE_BYTES, in4, tg4, (long long)bid + grid, ntiles, n4, tid);

    float s_box = 0.f, s_conf = 0.f, s_cls = 0.f;

    for (int j = 0; j < nt; j++) {
        // Stage j complete; stage j+1 may remain in flight.
        asm volatile("cp.async.wait_group 1;" ::: "memory");
        // Single barrier: proves all warps finished compute of tile j-1, which
        // read buffer (j-1)%3 == (j+2)%3 -> safe to refill it NOW, before compute.
        __syncthreads();
        issue_stage(dynbuf + ((j + 2) % NST) * STAGE_BYTES, in4, tg4,
                    (long long)bid + (long long)(j + 2) * grid, ntiles, n4, tid);

        char* sbase = dynbuf + (j % NST) * STAGE_BYTES;
        long long tile = (long long)bid + (long long)j * grid;
        long long cell = tile * CPT + tid;

        if (cell < ncells) {
            const float* sIn = (const float*)sbase;
            const float* sTg = (const float*)(sbase + TENSOR_F4 * 16);
            const float2* mi = reinterpret_cast<const float2*>(sIn + tid * CCH);
            const float2* mt = reinterpret_cast<const float2*>(sTg + tid * CCH);

            float a[10], t[10];
            #pragma unroll
            for (int i = 0; i < 5; i++) { float2 v = mi[i]; a[2*i] = v.x; a[2*i+1] = v.y; }
            #pragma unroll
            for (int i = 0; i < 5; i++) { float2 v = mt[i]; t[2*i] = v.x; t[2*i+1] = v.y; }

            float cls = 0.f;
            #pragma unroll
            for (int i = 5; i < 15; i++) {
                float2 va = mi[i], vb = mt[i];
                float dx = va.x - vb.x, dy = va.y - vb.y;
                cls += dx*dx + dy*dy;
            }

            float conf_t = t[4];
            float coord  = (conf_t > 0.f)  ? 1.f : 0.f;
            float noobj  = (conf_t == 0.f) ? 1.f : 0.f;

            float d0 = a[4] - t[4];
            float d1 = a[9] - t[9];
            float l_noobj = noobj * (d0*d0 + d1*d1);

            float txc = t[0] / 7.f, tyc = t[1] / 7.f, tw = t[2], th = t[3];
            float tx0 = txc - 0.5f*tw, ty0 = tyc - 0.5f*th;
            float tx1 = txc + 0.5f*tw, ty1 = tyc + 0.5f*th;
            float t_area = (tx1 - tx0) * (ty1 - ty0);

            float iou[2];
            #pragma unroll
            for (int b = 0; b < 2; b++) {
                int o = b * 5;
                float px = a[o+0] / 7.f, py = a[o+1] / 7.f, pw = a[o+2], ph = a[o+3];
                float x0 = px - 0.5f*pw, y0 = py - 0.5f*ph;
                float x1 = px + 0.5f*pw, y1 = py + 0.5f*ph;
                float lx = fmaxf(x0, tx0), ly = fmaxf(y0, ty0);
                float rx = fminf(x1, tx1), ry = fminf(y1, ty1);
                float wi = fmaxf(rx - lx, 0.f), hi = fmaxf(ry - ly, 0.f);
                float inter = wi * hi;
                float parea = (x1 - x0) * (y1 - y0);
                iou[b] = inter / (parea + t_area - inter);
            }

            bool sel1 = iou[1] > iou[0];              // jnp.argmax tie -> first
            float max_iou = fmaxf(iou[0], iou[1]);
            float r0 = sel1 ? a[5] : a[0];
            float r1 = sel1 ? a[6] : a[1];
            float r2 = sel1 ? a[7] : a[2];
            float r3 = sel1 ? a[8] : a[3];
            float r4 = sel1 ? a[9] : a[4];

            float dx = r0 - t[0], dy = r1 - t[1];
            float sw = sqrtf(r2) - sqrtf(t[2]);
            float sh = sqrtf(r3) - sqrtf(t[3]);
            float dobj = r4 - max_iou;

            s_box  += coord * (dx*dx + dy*dy + sw*sw + sh*sh);
            s_conf += coord * dobj*dobj + 0.5f * l_noobj;
            s_cls  += coord * cls;
        }
    }

    // ---- reduction: 4 warps -> smem -> thread 0 -> global atomics + ticket
    #pragma unroll
    for (int off = 16; off > 0; off >>= 1) {
        s_box  += __shfl_xor_sync(0xFFFFFFFFu, s_box,  off);
        s_conf += __shfl_xor_sync(0xFFFFFFFFu, s_conf, off);
        s_cls  += __shfl_xor_sync(0xFFFFFFFFu, s_cls,  off);
    }
    int wid = tid >> 5, lid = tid & 31;
    if (lid == 0) { sb[0][wid] = s_box; sb[1][wid] = s_conf; sb[2][wid] = s_cls; }
    __syncthreads();

    if (tid == 0) {
        float b0 = sb[0][0] + sb[0][1] + sb[0][2] + sb[0][3];
        float b1 = sb[1][0] + sb[1][1] + sb[1][2] + sb[1][3];
        float b2 = sb[2][0] + sb[2][1] + sb[2][2] + sb[2][3];
        atomicAdd(&g_acc[0], b0);
        atomicAdd(&g_acc[1], b1);
        atomicAdd(&g_acc[2], b2);
        __threadfence();
        unsigned int ticket = atomicAdd(&g_count, 1u);
        if (ticket == gridDim.x - 1) {
            float a0 = atomicExch(&g_acc[0], 0.f);
            float a1 = atomicExch(&g_acc[1], 0.f);
            float a2 = atomicExch(&g_acc[2], 0.f);
            out[0] = 0.5f * a0 * inv_bs;   // LAMBDA_COORD * (xy+wh) / bs
            out[1] = a1 * inv_bs;          // (obj + LAMBDA_NOOBJ*noobj) / bs
            out[2] = a2 * inv_bs;          // class / bs
            g_count = 0u;                  // reset for next graph replay
        }
    }
}

extern "C" void kernel_launch(void* const* d_in, const int* in_sizes, int n_in,
                              void* d_out, int out_size) {
    const float* in_ = (const float*)d_in[0];
    const float* tg_ = (const float*)d_in[1];
    float* out = (float*)d_out;

    int ncells = in_sizes[0] / CCH;            // B * GS * GS
    int bs = ncells / (GS * GS);
    float inv_bs = 1.0f / (float)bs;

    int ntiles = (ncells + CPT - 1) / CPT;     // 3136 for the bench shape

    // Opt-in dynamic smem above 48KB (idempotent; host-side, capture-safe).
    cudaFuncSetAttribute(yolo_loss_kernel,
                         cudaFuncAttributeMaxDynamicSharedMemorySize, DYN_SMEM);

    int blocks = 2 * 148;                      // 2 blocks/SM, work-strided tiles
    if (blocks > ntiles) blocks = ntiles;
    yolo_loss_kernel<<<blocks, TPB, DYN_SMEM>>>(in_, tg_, out, ncells, ntiles, inv_bs);
}

// round 12
// speedup vs baseline: 1.2020x; 1.2020x over previous
#include <cuda_runtime.h>
#include <cstdint>

#define GS 7
#define CCH 30
#define CPT 128                        // cells per tile
#define TPB 128                        // threads per block
#define NST 2                          // double buffer
#define TENSOR_F4 960                  // float4 per tensor per tile (128*30/4)
#define STAGE_F4 (2 * TENSOR_F4)       // 1920 (in + tg)
#define STAGE_BYTES (STAGE_F4 * 16)    // 30720
#define DYN_SMEM (NST * STAGE_BYTES)   // 61440 -> 3 blocks/SM
#define INV7 0.142857142857142857f

// Zero-initialized at module load; last-block finalize resets via atomicExch.
__device__ float g_acc[3];
__device__ unsigned int g_count;

__device__ __forceinline__ uint32_t smem_u32(const void* p) {
    return (uint32_t)__cvta_generic_to_shared(p);
}
__device__ __forceinline__ float fsqrt_fast(float x) {
    float y; asm("sqrt.approx.f32 %0, %1;" : "=f"(y) : "f"(x)); return y;
}

// Issue one stage's coalesced loads (all 128 threads participate), then commit
// a group. ALWAYS commits (possibly empty) so group counting stays uniform.
__device__ __forceinline__ void issue_stage(
    char* sbase, const float4* __restrict__ in4, const float4* __restrict__ tg4,
    long long tile, int ntiles, long long n4, int tid)
{
    if (tile < (long long)ntiles) {
        uint32_t dst = smem_u32(sbase);
        long long base4 = tile * TENSOR_F4;
        #pragma unroll
        for (int i = 0; i < 15; i++) {
            int g = i * TPB + tid;              // 0..1919 within stage
            const float4* src;
            long long s4;
            if (g < TENSOR_F4) { s4 = base4 + g;              src = in4 + s4; }
            else               { s4 = base4 + (g - TENSOR_F4); src = tg4 + s4; }
            if (s4 < n4) {
                asm volatile("cp.async.cg.shared.global [%0], [%1], 16;"
                             :: "r"(dst + (uint32_t)g * 16), "l"(src) : "memory");
            }
        }
    }
    asm volatile("cp.async.commit_group;" ::: "memory");
}

__global__ __launch_bounds__(TPB) void yolo_loss_kernel(
    const float* __restrict__ in_, const float* __restrict__ tg_,
    float* __restrict__ out, int ncells, int ntiles, float inv_bs)
{
    extern __shared__ __align__(16) char dynbuf[];
    __shared__ float sb[3][4];

    int tid = threadIdx.x;
    int bid = blockIdx.x;
    int grid = gridDim.x;
    const float4* in4 = reinterpret_cast<const float4*>(in_);
    const float4* tg4 = reinterpret_cast<const float4*>(tg_);
    long long n4 = ((long long)ncells * CCH) / 4;

    int nt = (bid < ntiles) ? (ntiles - bid + grid - 1) / grid : 0;

    // Prologue: fill both stages
    issue_stage(dynbuf + 0 * STAGE_BYTES, in4, tg4, (long long)bid,        ntiles, n4, tid);
    issue_stage(dynbuf + 1 * STAGE_BYTES, in4, tg4, (long long)bid + grid, ntiles, n4, tid);

    float s_box = 0.f, s_conf = 0.f, s_cls = 0.f;

    for (int j = 0; j < nt; j++) {
        // Stage j%2 complete; stage (j+1)%2 may remain in flight.
        asm volatile("cp.async.wait_group 1;" ::: "memory");
        __syncthreads();

        char* sbase = dynbuf + (j & 1) * STAGE_BYTES;
        long long tile = (long long)bid + (long long)j * grid;
        long long cell = tile * CPT + tid;

        if (cell < ncells) {
            const float* sIn = (const float*)sbase;
            const float* sTg = (const float*)(sbase + TENSOR_F4 * 16);
            const float2* mi = reinterpret_cast<const float2*>(sIn + tid * CCH);
            const float2* mt = reinterpret_cast<const float2*>(sTg + tid * CCH);

            float a[10], t[10];
            #pragma unroll
            for (int i = 0; i < 5; i++) { float2 v = mi[i]; a[2*i] = v.x; a[2*i+1] = v.y; }
            #pragma unroll
            for (int i = 0; i < 5; i++) { float2 v = mt[i]; t[2*i] = v.x; t[2*i+1] = v.y; }

            float cls = 0.f;
            #pragma unroll
            for (int i = 5; i < 15; i++) {
                float2 va = mi[i], vb = mt[i];
                float dx = va.x - vb.x, dy = va.y - vb.y;
                cls += dx*dx + dy*dy;
            }

            float conf_t = t[4];
            float coord  = (conf_t > 0.f)  ? 1.f : 0.f;
            float noobj  = (conf_t == 0.f) ? 1.f : 0.f;

            float d0 = a[4] - t[4];
            float d1 = a[9] - t[9];
            float l_noobj = noobj * (d0*d0 + d1*d1);

            // target box -> corners (xy scaled by 1/GS via multiply, wh raw)
            float txc = t[0] * INV7, tyc = t[1] * INV7, tw = t[2], th = t[3];
            float tx0 = txc - 0.5f*tw, ty0 = tyc - 0.5f*th;
            float tx1 = txc + 0.5f*tw, ty1 = tyc + 0.5f*th;
            float t_area = (tx1 - tx0) * (ty1 - ty0);

            float iou[2];
            #pragma unroll
            for (int b = 0; b < 2; b++) {
                int o = b * 5;
                float px = a[o+0] * INV7, py = a[o+1] * INV7, pw = a[o+2], ph = a[o+3];
                float x0 = px - 0.5f*pw, y0 = py - 0.5f*ph;
                float x1 = px + 0.5f*pw, y1 = py + 0.5f*ph;
                float lx = fmaxf(x0, tx0), ly = fmaxf(y0, ty0);
                float rx = fminf(x1, tx1), ry = fminf(y1, ty1);
                float wi = fmaxf(rx - lx, 0.f), hi = fmaxf(ry - ly, 0.f);
                float inter = wi * hi;
                float parea = (x1 - x0) * (y1 - y0);
                iou[b] = __fdividef(inter, parea + t_area - inter);
            }

            bool sel1 = iou[1] > iou[0];              // jnp.argmax tie -> first
            float max_iou = fmaxf(iou[0], iou[1]);
            float r0 = sel1 ? a[5] : a[0];
            float r1 = sel1 ? a[6] : a[1];
            float r2 = sel1 ? a[7] : a[2];
            float r3 = sel1 ? a[8] : a[3];
            float r4 = sel1 ? a[9] : a[4];

            float dx = r0 - t[0], dy = r1 - t[1];
            float sw = fsqrt_fast(r2) - fsqrt_fast(t[2]);
            float sh = fsqrt_fast(r3) - fsqrt_fast(t[3]);
            float dobj = r4 - max_iou;

            s_box  += coord * (dx*dx + dy*dy + sw*sw + sh*sh);
            s_conf += coord * dobj*dobj + 0.5f * l_noobj;
            s_cls  += coord * cls;
        }

        __syncthreads();   // all threads done with stage j&1 before refilling it
        issue_stage(dynbuf + (j & 1) * STAGE_BYTES, in4, tg4,
                    (long long)bid + (long long)(j + 2) * grid, ntiles, n4, tid);
    }

    // ---- reduction: 4 warps -> smem -> thread 0 -> global atomics + ticket
    #pragma unroll
    for (int off = 16; off > 0; off >>= 1) {
        s_box  += __shfl_xor_sync(0xFFFFFFFFu, s_box,  off);
        s_conf += __shfl_xor_sync(0xFFFFFFFFu, s_conf, off);
        s_cls  += __shfl_xor_sync(0xFFFFFFFFu, s_cls,  off);
    }
    int wid = tid >> 5, lid = tid & 31;
    if (lid == 0) { sb[0][wid] = s_box; sb[1][wid] = s_conf; sb[2][wid] = s_cls; }
    __syncthreads();

    if (tid == 0) {
        float b0 = sb[0][0] + sb[0][1] + sb[0][2] + sb[0][3];
        float b1 = sb[1][0] + sb[1][1] + sb[1][2] + sb[1][3];
        float b2 = sb[2][0] + sb[2][1] + sb[2][2] + sb[2][3];
        atomicAdd(&g_acc[0], b0);
        atomicAdd(&g_acc[1], b1);
        atomicAdd(&g_acc[2], b2);
        __threadfence();
        unsigned int ticket = atomicAdd(&g_count, 1u);
        if (ticket == gridDim.x - 1) {
            float a0 = atomicExch(&g_acc[0], 0.f);
            float a1 = atomicExch(&g_acc[1], 0.f);
            float a2 = atomicExch(&g_acc[2], 0.f);
            out[0] = 0.5f * a0 * inv_bs;   // LAMBDA_COORD * (xy+wh) / bs
            out[1] = a1 * inv_bs;          // (obj + LAMBDA_NOOBJ*noobj) / bs
            out[2] = a2 * inv_bs;          // class / bs
            g_count = 0u;                  // reset for next graph replay
        }
    }
}

extern "C" void kernel_launch(void* const* d_in, const int* in_sizes, int n_in,
                              void* d_out, int out_size) {
    const float* in_ = (const float*)d_in[0];
    const float* tg_ = (const float*)d_in[1];
    float* out = (float*)d_out;

    int ncells = in_sizes[0] / CCH;            // B * GS * GS
    int bs = ncells / (GS * GS);
    float inv_bs = 1.0f / (float)bs;

    int ntiles = (ncells + CPT - 1) / CPT;     // 3136 for the bench shape

    // Opt-in dynamic smem above 48KB (idempotent; host-side, capture-safe).
    cudaFuncSetAttribute(yolo_loss_kernel,
                         cudaFuncAttributeMaxDynamicSharedMemorySize, DYN_SMEM);

    int blocks = 3 * 148;                      // 3 blocks/SM (61KB each), 12 warps/SM
    if (blocks > ntiles) blocks = ntiles;
    yolo_loss_kernel<<<blocks, TPB, DYN_SMEM>>>(in_, tg_, out, ncells, ntiles, inv_bs);
}